// round 2
// baseline (speedup 1.0000x reference)
#include <cuda_runtime.h>
#include <cstdint>

#define N_BUSES 2000
#define HASH_BITS 19
#define HASH_SIZE (1 << HASH_BITS)
#define HASH_MASK (HASH_SIZE - 1)
#define MAX_EDGES 262144
#define MAX_BN    131072
#define MAX_B     64
#define NT        256
#define GRID      296        // <= 148 SMs * 2 CTAs/SM (GB300 has 152 SMs) -> always co-resident

// Static device scratch (zero-initialized at module load; no runtime allocation).
__device__ unsigned long long g_hash[HASH_SIZE];   // (key+1)<<32 | (edge+1); 0 = empty
__device__ int2               g_einfo[MAX_EDGES];  // {slot, (b<<22)|(i<<11)|j}
__device__ float2             g_YV[MAX_BN];        // per-bus YV accumulator (complex)
__device__ float2             g_Smean[MAX_B];      // per-batch mean of S (complex)
__device__ float              g_Vmmean[MAX_B];     // per-batch mean of Vm
__device__ double             g_acc[8];            // d1re, d1im, d2, d3, mse
__device__ unsigned           g_cnt;               // barrier arrival counter
__device__ unsigned           g_gen;               // barrier generation (monotonic across replays)

__device__ __forceinline__ void grid_barrier()
{
    __syncthreads();
    if (threadIdx.x == 0) {
        __threadfence();                               // publish this block's phase writes
        volatile unsigned* genp = &g_gen;
        const unsigned gen = *genp;
        if (atomicAdd(&g_cnt, 1u) == GRID - 1u) {
            g_cnt = 0u;
            __threadfence();                           // cnt reset visible before gen bump
            *genp = gen + 1u;
        } else {
            while (*genp == gen) { __nanosleep(32); }
        }
        __threadfence();                               // acquire: other blocks' writes visible
    }
    __syncthreads();
}

__global__ void __launch_bounds__(NT, 2)
fused_loss(const float* __restrict__ x,
           const float* __restrict__ ea,
           const int*   __restrict__ ei,
           const float* __restrict__ outputs,
           const float* __restrict__ labels,
           float* __restrict__ out, int out_size,
           int B, int BN, int BE, int E)
{
    const int tid  = threadIdx.x;
    const int gtid = blockIdx.x * NT + tid;
    const int NTH  = GRID * NT;
    const int lane = tid & 31, wid = tid >> 5;

    // ====================== PHASE 0 ======================
    // (a) blocks [0,B): per-batch means of S and Vm  (direct write, no zeroing needed)
    if (blockIdx.x < B) {
        const int b = blockIdx.x;
        float sr = 0.f, si = 0.f, vm = 0.f;
        for (int i = tid; i < N_BUSES; i += NT) {
            const float* p = x + (size_t)(b * N_BUSES + i) * 6;
            sr += p[0]; si += p[1]; vm += p[2];
        }
        for (int o = 16; o > 0; o >>= 1) {
            sr += __shfl_down_sync(0xffffffffu, sr, o);
            si += __shfl_down_sync(0xffffffffu, si, o);
            vm += __shfl_down_sync(0xffffffffu, vm, o);
        }
        __shared__ float shm[3][NT / 32];
        if (lane == 0) { shm[0][wid] = sr; shm[1][wid] = si; shm[2][wid] = vm; }
        __syncthreads();
        if (wid == 0) {
            sr = (lane < NT / 32) ? shm[0][lane] : 0.f;
            si = (lane < NT / 32) ? shm[1][lane] : 0.f;
            vm = (lane < NT / 32) ? shm[2][lane] : 0.f;
            for (int o = 4; o > 0; o >>= 1) {
                sr += __shfl_down_sync(0xffffffffu, sr, o);
                si += __shfl_down_sync(0xffffffffu, si, o);
                vm += __shfl_down_sync(0xffffffffu, vm, o);
            }
            if (lane == 0) {
                const float inv = 1.0f / (float)N_BUSES;
                g_Smean[b]  = make_float2(sr * inv, si * inv);
                g_Vmmean[b] = vm * inv;
            }
        }
    }

    // (b) zero YV + scalar accumulators
    for (int i = gtid; i < BN; i += NTH) g_YV[i] = make_float2(0.f, 0.f);
    if (gtid < 8) g_acc[gtid] = 0.0;

    // (c) hash insert: last-write-wins, priority = global edge index
    //     (hash was cleared by the previous replay's phase 2; zero-init on first run)
    for (int e = gtid; e < BE; e += NTH) {
        const int i = ei[e]      % N_BUSES;
        const int j = ei[BE + e] % N_BUSES;
        const int b = e / E;
        const unsigned key  = (unsigned)((b * N_BUSES + i) * N_BUSES + j); // < 2^27
        const unsigned key1 = key + 1u;
        const unsigned long long newval =
            ((unsigned long long)key1 << 32) | (unsigned)(e + 1);
        int slot = (int)((key * 2654435761u) >> (32 - HASH_BITS)) & HASH_MASK;
        for (;;) {
            unsigned long long prev = atomicCAS(&g_hash[slot], 0ULL, newval);
            if (prev == 0ULL) break;
            if ((unsigned)(prev >> 32) == key1) { atomicMax(&g_hash[slot], newval); break; }
            slot = (slot + 1) & HASH_MASK;
        }
        g_einfo[e] = make_int2(slot, (b << 22) | (i << 11) | j);
    }

    grid_barrier();

    // ====================== PHASE 1 ======================
    // winning edges scatter adm * V[b,j] into YV[b,i]
    for (int e = gtid; e < BE; e += NTH) {
        const int2 info = g_einfo[e];
        const unsigned long long v = g_hash[info.x];
        if ((unsigned)(v & 0xffffffffu) != (unsigned)(e + 1)) continue;  // superseded dup
        const int j = info.y & 2047;
        const int i = (info.y >> 11) & 2047;
        const int b = info.y >> 22;
        const float ar = ea[2 * e], ai = ea[2 * e + 1];
        const int jj = b * N_BUSES + j;
        const float vr = outputs[2 * jj], vi = outputs[2 * jj + 1];
        const int ii = b * N_BUSES + i;
        atomicAdd(&g_YV[ii].x, ar * vr - ai * vi);
        atomicAdd(&g_YV[ii].y, ar * vi + ai * vr);
    }

    grid_barrier();

    // ====================== PHASE 2 ======================
    // (a) hash cleanup for next replay (overlaps with terms)
    for (int e = gtid; e < BE; e += NTH) g_hash[g_einfo[e].x] = 0ULL;

    // (b) per-bus physics terms + MSE, f64 block reduction into g_acc
    double a0 = 0, a1 = 0, a2 = 0, a3 = 0, a4 = 0;
    for (int idx = gtid; idx < BN; idx += NTH) {
        const int b = idx / N_BUSES;
        const float vr = outputs[2 * idx], vi = outputs[2 * idx + 1];
        const float2 yv = g_YV[idx];
        const float sp_re = vr * yv.x + vi * yv.y;    // Spred = V * conj(YV)
        const float sp_im = vi * yv.x - vr * yv.y;
        const float* p = x + (size_t)idx * 6;
        const float sr = p[0], si = p[1], vm = p[2];
        const float bt0 = p[3], bt1 = p[4], bt2 = p[5];

        float sn;
        if (sr != 0.f || si != 0.f) {
            sn = 1.f / sqrtf(sr * sr + si * si);
        } else {
            const float2 sm = g_Smean[b];
            sn = 1.f / sqrtf(sm.x * sm.x + sm.y * sm.y);
        }
        const float dr = sp_re - sr, di = sp_im - si;
        const float r1r = (dr * dr - di * di) * bt0;  // complex (d)^2 * bt0
        const float r1i = (2.f * dr * di) * bt0;
        const float r2  = dr * dr * bt1;              // real
        a0 += (double)(sn * (r1r + r2));
        a1 += (double)(sn * r1i);

        const float vminv = (vm != 0.f) ? (1.f / vm) : (1.f / g_Vmmean[b]);
        const float vmag  = sqrtf(vr * vr + vi * vi);
        a2 += (double)(fabsf(vmag * (bt1 + bt2) - vm) * vminv);
        a3 += (double)(fabsf(vi * bt2) * vminv);

        const float l0 = labels[2 * idx], l1 = labels[2 * idx + 1];
        const float e0 = vr - l0, e1 = vi - l1;
        a4 += (double)(e0 * e0) + (double)(e1 * e1);
    }

    for (int o = 16; o > 0; o >>= 1) {
        a0 += __shfl_down_sync(0xffffffffu, a0, o);
        a1 += __shfl_down_sync(0xffffffffu, a1, o);
        a2 += __shfl_down_sync(0xffffffffu, a2, o);
        a3 += __shfl_down_sync(0xffffffffu, a3, o);
        a4 += __shfl_down_sync(0xffffffffu, a4, o);
    }
    __shared__ double shd[5][NT / 32];
    if (lane == 0) {
        shd[0][wid] = a0; shd[1][wid] = a1; shd[2][wid] = a2;
        shd[3][wid] = a3; shd[4][wid] = a4;
    }
    __syncthreads();
    if (wid == 0) {
        a0 = (lane < NT / 32) ? shd[0][lane] : 0.0;
        a1 = (lane < NT / 32) ? shd[1][lane] : 0.0;
        a2 = (lane < NT / 32) ? shd[2][lane] : 0.0;
        a3 = (lane < NT / 32) ? shd[3][lane] : 0.0;
        a4 = (lane < NT / 32) ? shd[4][lane] : 0.0;
        for (int o = 4; o > 0; o >>= 1) {
            a0 += __shfl_down_sync(0xffffffffu, a0, o);
            a1 += __shfl_down_sync(0xffffffffu, a1, o);
            a2 += __shfl_down_sync(0xffffffffu, a2, o);
            a3 += __shfl_down_sync(0xffffffffu, a3, o);
            a4 += __shfl_down_sync(0xffffffffu, a4, o);
        }
        if (lane == 0) {
            atomicAdd(&g_acc[0], a0);
            atomicAdd(&g_acc[1], a1);
            atomicAdd(&g_acc[2], a2);
            atomicAdd(&g_acc[3], a3);
            atomicAdd(&g_acc[4], a4);
        }
    }

    grid_barrier();

    // ====================== FINALIZE ======================
    if (gtid == 0) {
        const double inv = 1.0 / (double)BN;
        const double d1r = g_acc[0] * inv;
        const double d1i = g_acc[1] * inv;
        const double d2  = g_acc[2] * inv;
        const double d3  = g_acc[3] * inv;
        const double mse = g_acc[4] / (double)(2 * BN);
        const double pr = d1r + d2 + d3;   // W1=W2=W3=1
        const double pi = d1i;
        const double lr = mse + 0.1 * pr;  // LMBDA = 0.1
        const double li = 0.1 * pi;
        if (out_size >= 10) {
            out[0] = (float)lr;  out[1] = (float)li;
            out[2] = (float)pr;  out[3] = (float)pi;
            out[4] = (float)d1r; out[5] = (float)d1i;
            out[6] = (float)d2;  out[7] = 0.f;
            out[8] = (float)d3;  out[9] = 0.f;
        } else {
            out[0] = (float)lr;
            if (out_size > 1) out[1] = (float)pr;
            if (out_size > 2) out[2] = (float)d1r;
            if (out_size > 3) out[3] = (float)d2;
            if (out_size > 4) out[4] = (float)d3;
        }
    }
}

// ---------------------------------------------------------------------------
extern "C" void kernel_launch(void* const* d_in, const int* in_sizes, int n_in,
                              void* d_out, int out_size)
{
    const float* x       = (const float*)d_in[0];
    const float* ea      = (const float*)d_in[1];
    const int*   ei      = (const int*)  d_in[2];
    const float* outputs = (const float*)d_in[3];
    const float* labels  = (const float*)d_in[4];

    const int BN = in_sizes[3] / 2;        // B * N_BUSES
    const int B  = BN / N_BUSES;
    const int BE = in_sizes[2] / 2;        // B * E
    const int E  = BE / B;

    fused_loss<<<GRID, NT>>>(x, ea, ei, outputs, labels,
                             (float*)d_out, out_size, B, BN, BE, E);
}

// round 6
// speedup vs baseline: 1.2616x; 1.2616x over previous
#include <cuda_runtime.h>
#include <cstdint>

#define N_BUSES 2000
#define HASH_BITS 19
#define HASH_SIZE (1 << HASH_BITS)
#define HASH_MASK (HASH_SIZE - 1)
#define MAX_BN     131072
#define MAX_B      64
#define MAX_LOSERS 8192
#define NT         256
#define TAG_SHIFT  45
#define KEY_SHIFT  18
#define EDGE_MASK  0x3FFFFull          // 18 bits
#define KEY_MASK   0x7FFFFFFu          // 27 bits

// Static device scratch (zero-initialized at module load; no runtime allocation).
__device__ unsigned long long g_hash[HASH_SIZE];  // (epoch<<45)|(key<<18)|(edge+1)
__device__ int                g_losers[MAX_LOSERS];
__device__ int                g_nlos;
__device__ float2             g_YV[MAX_BN];       // per-bus YV accumulator (complex)
__device__ float2             g_Smean[MAX_B];
__device__ float              g_Vmmean[MAX_B];
__device__ double             g_acc[8];           // d1re, d1im, d2, d3, mse
__device__ unsigned           g_epoch;            // bumped once per call (finalize)
__device__ unsigned           g_done1, g_done2;   // last-block-done counters

// ---------------------------------------------------------------------------
// K1: per-batch means | epoch-hash insert (+loser detect) | unconditional
//     YV scatter-adds. Last finished block subtracts loser contributions.
// ---------------------------------------------------------------------------
__global__ void k1_build(const float* __restrict__ x,
                         const float* __restrict__ ea,
                         const int*   __restrict__ ei,
                         const float* __restrict__ outputs,
                         int B, int BE, int E)
{
    const int tid = threadIdx.x;
    const int lane = tid & 31, wid = tid >> 5;
    const unsigned tag = g_epoch + 1u;            // current-call tag (>=1)

    // --- blocks [0,B): per-batch means of S and Vm ---
    if (blockIdx.x < B) {
        const int b = blockIdx.x;
        float sr = 0.f, si = 0.f, vm = 0.f;
        for (int i = tid; i < N_BUSES; i += NT) {
            const float* p = x + (size_t)(b * N_BUSES + i) * 6;
            sr += p[0]; si += p[1]; vm += p[2];
        }
        for (int o = 16; o > 0; o >>= 1) {
            sr += __shfl_down_sync(0xffffffffu, sr, o);
            si += __shfl_down_sync(0xffffffffu, si, o);
            vm += __shfl_down_sync(0xffffffffu, vm, o);
        }
        __shared__ float shm[3][NT / 32];
        if (lane == 0) { shm[0][wid] = sr; shm[1][wid] = si; shm[2][wid] = vm; }
        __syncthreads();
        if (wid == 0) {
            sr = (lane < NT / 32) ? shm[0][lane] : 0.f;
            si = (lane < NT / 32) ? shm[1][lane] : 0.f;
            vm = (lane < NT / 32) ? shm[2][lane] : 0.f;
            for (int o = 4; o > 0; o >>= 1) {
                sr += __shfl_down_sync(0xffffffffu, sr, o);
                si += __shfl_down_sync(0xffffffffu, si, o);
                vm += __shfl_down_sync(0xffffffffu, vm, o);
            }
            if (lane == 0) {
                const float inv = 1.0f / (float)N_BUSES;
                g_Smean[b]  = make_float2(sr * inv, si * inv);
                g_Vmmean[b] = vm * inv;
            }
        }
    }

    // --- one edge per thread ---
    const int e = blockIdx.x * NT + tid;
    if (e < BE) {
        const int i = ei[e]      % N_BUSES;
        const int j = ei[BE + e] % N_BUSES;
        const int b = e / E;

        // unconditional scatter-add of adm * V[b,j] into YV[b,i]
        const float2 a2v = *(const float2*)(ea + 2 * e);
        const float2 v2  = *(const float2*)(outputs + 2 * (b * N_BUSES + j));
        const int ii = b * N_BUSES + i;
        atomicAdd(&g_YV[ii].x, a2v.x * v2.x - a2v.y * v2.y);
        atomicAdd(&g_YV[ii].y, a2v.x * v2.y + a2v.y * v2.x);

        // epoch-hash insert: last-write-wins, record losers
        const unsigned key = (unsigned)((b * N_BUSES + i) * N_BUSES + j); // < 2^27
        const unsigned long long newval =
            ((unsigned long long)tag << TAG_SHIFT) |
            ((unsigned long long)key << KEY_SHIFT) | (unsigned)(e + 1);
        int slot = (int)((key * 2654435761u) >> (32 - HASH_BITS)) & HASH_MASK;
        unsigned long long v = __ldcg(&g_hash[slot]);
        for (;;) {
            if ((unsigned)(v >> TAG_SHIFT) != tag) {         // stale/empty: claim
                unsigned long long prev = atomicCAS(&g_hash[slot], v, newval);
                if (prev == v) break;
                v = prev;                                     // re-examine slot
                continue;
            }
            if ((unsigned)((v >> KEY_SHIFT) & KEY_MASK) == key) {  // dup key
                unsigned long long old = atomicMax(&g_hash[slot], newval);
                // slot key-stable within epoch => old has same tag+key
                const int loser = (old > newval) ? e : (int)(old & EDGE_MASK) - 1;
                const int li = atomicAdd(&g_nlos, 1);
                if (li < MAX_LOSERS) g_losers[li] = loser;
                break;
            }
            slot = (slot + 1) & HASH_MASK;                   // other key: probe on
            v = __ldcg(&g_hash[slot]);
        }
    }

    // --- last-finished block subtracts loser contributions ---
    __shared__ int s_last;
    __syncthreads();
    if (tid == 0) {
        __threadfence();
        s_last = (atomicAdd(&g_done1, 1u) == gridDim.x - 1u);
    }
    __syncthreads();
    if (s_last) {
        const int n = g_nlos;
        for (int t = tid; t < n && t < MAX_LOSERS; t += NT) {
            const int le = g_losers[t];
            const int i = ei[le]      % N_BUSES;
            const int j = ei[BE + le] % N_BUSES;
            const int b = le / E;
            const float2 a2v = *(const float2*)(ea + 2 * le);
            const float2 v2  = *(const float2*)(outputs + 2 * (b * N_BUSES + j));
            const int ii = b * N_BUSES + i;
            atomicAdd(&g_YV[ii].x, -(a2v.x * v2.x - a2v.y * v2.y));
            atomicAdd(&g_YV[ii].y, -(a2v.x * v2.y + a2v.y * v2.x));
        }
        __syncthreads();
        if (tid == 0) { g_done1 = 0u; g_nlos = 0; }
    }
}

// ---------------------------------------------------------------------------
// K3: per-bus physics terms + MSE, read-then-clear YV, reduce into g_acc;
//     last block finalizes scalars, resets acc, bumps epoch.
// ---------------------------------------------------------------------------
__global__ void k3_terms(const float* __restrict__ x,
                         const float* __restrict__ outputs,
                         const float* __restrict__ labels,
                         float* __restrict__ out, int out_size, int BN)
{
    const int tid = threadIdx.x;
    const int idx = blockIdx.x * NT + tid;
    const int lane = tid & 31, wid = tid >> 5;
    double a0 = 0, a1 = 0, a2 = 0, a3 = 0, a4 = 0;

    if (idx < BN) {
        const int b = idx / N_BUSES;
        const float2 v2 = *(const float2*)(outputs + 2 * idx);
        const float vr = v2.x, vi = v2.y;
        const float2 yv = g_YV[idx];
        g_YV[idx] = make_float2(0.f, 0.f);            // clean for next call
        const float sp_re = vr * yv.x + vi * yv.y;    // Spred = V * conj(YV)
        const float sp_im = vi * yv.x - vr * yv.y;
        const float* p = x + (size_t)idx * 6;
        const float sr = p[0], si = p[1], vm = p[2];
        const float bt0 = p[3], bt1 = p[4], bt2 = p[5];

        float sn;
        if (sr != 0.f || si != 0.f) {
            sn = 1.f / sqrtf(sr * sr + si * si);
        } else {
            const float2 sm = g_Smean[b];
            sn = 1.f / sqrtf(sm.x * sm.x + sm.y * sm.y);
        }
        const float dr = sp_re - sr, di = sp_im - si;
        const float r1r = (dr * dr - di * di) * bt0;  // complex (d)^2 * bt0
        const float r1i = (2.f * dr * di) * bt0;
        const float r2  = dr * dr * bt1;              // real part only
        a0 = (double)(sn * (r1r + r2));
        a1 = (double)(sn * r1i);

        const float vminv = (vm != 0.f) ? (1.f / vm) : (1.f / g_Vmmean[b]);
        const float vmag  = sqrtf(vr * vr + vi * vi);
        a2 = (double)(fabsf(vmag * (bt1 + bt2) - vm) * vminv);
        a3 = (double)(fabsf(vi * bt2) * vminv);

        const float2 l2 = *(const float2*)(labels + 2 * idx);
        const float e0 = vr - l2.x, e1 = vi - l2.y;
        a4 = (double)(e0 * e0) + (double)(e1 * e1);
    }

    for (int o = 16; o > 0; o >>= 1) {
        a0 += __shfl_down_sync(0xffffffffu, a0, o);
        a1 += __shfl_down_sync(0xffffffffu, a1, o);
        a2 += __shfl_down_sync(0xffffffffu, a2, o);
        a3 += __shfl_down_sync(0xffffffffu, a3, o);
        a4 += __shfl_down_sync(0xffffffffu, a4, o);
    }
    __shared__ double shd[5][NT / 32];
    if (lane == 0) {
        shd[0][wid] = a0; shd[1][wid] = a1; shd[2][wid] = a2;
        shd[3][wid] = a3; shd[4][wid] = a4;
    }
    __syncthreads();
    if (wid == 0) {
        a0 = (lane < NT / 32) ? shd[0][lane] : 0.0;
        a1 = (lane < NT / 32) ? shd[1][lane] : 0.0;
        a2 = (lane < NT / 32) ? shd[2][lane] : 0.0;
        a3 = (lane < NT / 32) ? shd[3][lane] : 0.0;
        a4 = (lane < NT / 32) ? shd[4][lane] : 0.0;
        for (int o = 4; o > 0; o >>= 1) {
            a0 += __shfl_down_sync(0xffffffffu, a0, o);
            a1 += __shfl_down_sync(0xffffffffu, a1, o);
            a2 += __shfl_down_sync(0xffffffffu, a2, o);
            a3 += __shfl_down_sync(0xffffffffu, a3, o);
            a4 += __shfl_down_sync(0xffffffffu, a4, o);
        }
        if (lane == 0) {
            atomicAdd(&g_acc[0], a0);
            atomicAdd(&g_acc[1], a1);
            atomicAdd(&g_acc[2], a2);
            atomicAdd(&g_acc[3], a3);
            atomicAdd(&g_acc[4], a4);
        }
    }

    // --- last block finalizes ---
    __shared__ int s_last;
    __syncthreads();
    if (tid == 0) {
        __threadfence();
        s_last = (atomicAdd(&g_done2, 1u) == gridDim.x - 1u);
    }
    __syncthreads();
    if (s_last && tid == 0) {
        const double inv = 1.0 / (double)BN;
        const double d1r = g_acc[0] * inv;
        const double d1i = g_acc[1] * inv;
        const double d2  = g_acc[2] * inv;
        const double d3  = g_acc[3] * inv;
        const double mse = g_acc[4] / (double)(2 * BN);
        const double pr = d1r + d2 + d3;   // W1=W2=W3=1
        const double pi = d1i;
        const double lr = mse + 0.1 * pr;  // LMBDA = 0.1
        const double li = 0.1 * pi;
        if (out_size >= 10) {
            out[0] = (float)lr;  out[1] = (float)li;
            out[2] = (float)pr;  out[3] = (float)pi;
            out[4] = (float)d1r; out[5] = (float)d1i;
            out[6] = (float)d2;  out[7] = 0.f;
            out[8] = (float)d3;  out[9] = 0.f;
        } else {
            out[0] = (float)lr;
            if (out_size > 1) out[1] = (float)pr;
            if (out_size > 2) out[2] = (float)d1r;
            if (out_size > 3) out[3] = (float)d2;
            if (out_size > 4) out[4] = (float)d3;
        }
        for (int t = 0; t < 5; t++) g_acc[t] = 0.0;   // ready for next call
        g_done2 = 0u;
        g_epoch = g_epoch + 1u;                       // invalidate hash entries
    }
}

// ---------------------------------------------------------------------------
extern "C" void kernel_launch(void* const* d_in, const int* in_sizes, int n_in,
                              void* d_out, int out_size)
{
    const float* x       = (const float*)d_in[0];
    const float* ea      = (const float*)d_in[1];
    const int*   ei      = (const int*)  d_in[2];
    const float* outputs = (const float*)d_in[3];
    const float* labels  = (const float*)d_in[4];

    const int BN = in_sizes[3] / 2;        // B * N_BUSES
    const int B  = BN / N_BUSES;
    const int BE = in_sizes[2] / 2;        // B * E
    const int E  = BE / B;

    const int nbEdge = (BE + NT - 1) / NT;
    const int nbBus  = (BN + NT - 1) / NT;

    k1_build<<<nbEdge, NT>>>(x, ea, ei, outputs, B, BE, E);
    k3_terms<<<nbBus,  NT>>>(x, outputs, labels, (float*)d_out, out_size, BN);
}

// round 7
// speedup vs baseline: 1.5543x; 1.2320x over previous
#include <cuda_runtime.h>
#include <cstdint>

#define N_BUSES 2000
#define MAX_BN     131072
#define MAX_B      64
#define MAX_LOSERS 8192
#define MAX_BLOCKS 1024
#define NT         256
#define TAB_BITS   27
#define TAB_SIZE   (1 << TAB_BITS)      // 128M entries (keys < 32*2000*2000 < 2^27)
#define EDGE_BITS  18
#define EDGE_MASK  0x3FFFFull

// Static device scratch (zero-initialized at module load; no runtime allocation).
__device__ unsigned long long g_tab[TAB_SIZE];    // (epoch<<18)|(edge+1); direct-mapped by key
__device__ int                g_losers[MAX_LOSERS];
__device__ int                g_nlos;
__device__ float2             g_YV[MAX_BN];       // per-bus YV accumulator (complex)
__device__ float2             g_Smean[MAX_B];
__device__ float              g_Vmmean[MAX_B];
__device__ double             g_part[MAX_BLOCKS][5];  // per-block partials (k3)
__device__ unsigned long long g_epoch;            // bumped once per call (k3 finalize)
__device__ unsigned           g_done1, g_done2;   // last-block-done counters

__device__ __forceinline__ void red_add_v2(float2* addr, float vx, float vy)
{
    asm volatile("red.global.add.v2.f32 [%0], {%1, %2};"
                 :: "l"(addr), "f"(vx), "f"(vy) : "memory");
}

// ---------------------------------------------------------------------------
// K1: per-batch means | direct-table dedup (one atomicMax/edge) |
//     unconditional YV scatter (red.v2). Last-done block subtracts losers.
// ---------------------------------------------------------------------------
__global__ void k1_build(const float* __restrict__ x,
                         const float* __restrict__ ea,
                         const int*   __restrict__ ei,
                         const float* __restrict__ outputs,
                         int B, int BE, int E)
{
    const int tid = threadIdx.x;
    const int lane = tid & 31, wid = tid >> 5;
    const unsigned long long tag = g_epoch + 1ull;   // current-call tag (>=1)

    // --- blocks [0,B): per-batch means of S and Vm (runs alongside edge work) ---
    if (blockIdx.x < B) {
        const int b = blockIdx.x;
        float sr = 0.f, si = 0.f, vm = 0.f;
        for (int i = tid; i < N_BUSES; i += NT) {
            const float* p = x + (size_t)(b * N_BUSES + i) * 6;
            sr += p[0]; si += p[1]; vm += p[2];
        }
        for (int o = 16; o > 0; o >>= 1) {
            sr += __shfl_down_sync(0xffffffffu, sr, o);
            si += __shfl_down_sync(0xffffffffu, si, o);
            vm += __shfl_down_sync(0xffffffffu, vm, o);
        }
        __shared__ float shm[3][NT / 32];
        if (lane == 0) { shm[0][wid] = sr; shm[1][wid] = si; shm[2][wid] = vm; }
        __syncthreads();
        if (wid == 0) {
            sr = (lane < NT / 32) ? shm[0][lane] : 0.f;
            si = (lane < NT / 32) ? shm[1][lane] : 0.f;
            vm = (lane < NT / 32) ? shm[2][lane] : 0.f;
            for (int o = 4; o > 0; o >>= 1) {
                sr += __shfl_down_sync(0xffffffffu, sr, o);
                si += __shfl_down_sync(0xffffffffu, si, o);
                vm += __shfl_down_sync(0xffffffffu, vm, o);
            }
            if (lane == 0) {
                const float inv = 1.0f / (float)N_BUSES;
                g_Smean[b]  = make_float2(sr * inv, si * inv);
                g_Vmmean[b] = vm * inv;
            }
        }
    }

    // --- one edge per thread ---
    const int e = blockIdx.x * NT + tid;
    if (e < BE) {
        const int i = ei[e]      % N_BUSES;
        const int j = ei[BE + e] % N_BUSES;
        const int b = e / E;

        // unconditional scatter-add of adm * V[b,j] into YV[b,i] (fire-and-forget)
        const float2 a2v = *(const float2*)(ea + 2 * e);
        const float2 v2  = *(const float2*)(outputs + 2 * (b * N_BUSES + j));
        red_add_v2(&g_YV[b * N_BUSES + i],
                   a2v.x * v2.x - a2v.y * v2.y,
                   a2v.x * v2.y + a2v.y * v2.x);

        // direct-mapped dedup: ONE atomicMax; same-epoch old => duplicate key
        const int key = (b * N_BUSES + i) * N_BUSES + j;     // < 2^27
        const unsigned long long newval = (tag << EDGE_BITS) | (unsigned)(e + 1);
        const unsigned long long old = atomicMax(&g_tab[key], newval);
        if ((old >> EDGE_BITS) == tag) {                      // duplicate this call
            const int loser = (old > newval) ? e : (int)(old & EDGE_MASK) - 1;
            const int li = atomicAdd(&g_nlos, 1);
            if (li < MAX_LOSERS) g_losers[li] = loser;
        }
    }

    // --- last-finished block subtracts loser contributions ---
    __shared__ int s_last;
    __syncthreads();
    if (tid == 0) {
        __threadfence();
        s_last = (atomicAdd(&g_done1, 1u) == gridDim.x - 1u);
    }
    __syncthreads();
    if (s_last) {
        __threadfence();
        const int n = g_nlos;
        for (int t = tid; t < n && t < MAX_LOSERS; t += NT) {
            const int le = g_losers[t];
            const int i = ei[le]      % N_BUSES;
            const int j = ei[BE + le] % N_BUSES;
            const int b = le / E;
            const float2 a2v = *(const float2*)(ea + 2 * le);
            const float2 v2  = *(const float2*)(outputs + 2 * (b * N_BUSES + j));
            red_add_v2(&g_YV[b * N_BUSES + i],
                       -(a2v.x * v2.x - a2v.y * v2.y),
                       -(a2v.x * v2.y + a2v.y * v2.x));
        }
        __syncthreads();
        if (tid == 0) { g_done1 = 0u; g_nlos = 0; }
    }
}

// ---------------------------------------------------------------------------
// K3: per-bus terms + MSE -> per-block f64 partials (plain stores);
//     last-done block reduces partials, finalizes, resets state.
// ---------------------------------------------------------------------------
__global__ void k3_terms(const float* __restrict__ x,
                         const float* __restrict__ outputs,
                         const float* __restrict__ labels,
                         float* __restrict__ out, int out_size, int BN)
{
    const int tid = threadIdx.x;
    const int idx = blockIdx.x * NT + tid;
    const int lane = tid & 31, wid = tid >> 5;
    double a0 = 0, a1 = 0, a2 = 0, a3 = 0, a4 = 0;

    if (idx < BN) {
        const int b = idx / N_BUSES;
        const float2 v2 = *(const float2*)(outputs + 2 * idx);
        const float vr = v2.x, vi = v2.y;
        const float2 yv = g_YV[idx];
        g_YV[idx] = make_float2(0.f, 0.f);            // clean for next call
        const float sp_re = vr * yv.x + vi * yv.y;    // Spred = V * conj(YV)
        const float sp_im = vi * yv.x - vr * yv.y;
        const float2* px = (const float2*)(x + (size_t)idx * 6);
        const float2 x01 = px[0], x23 = px[1], x45 = px[2];
        const float sr = x01.x, si = x01.y, vm = x23.x;
        const float bt0 = x23.y, bt1 = x45.x, bt2 = x45.y;

        float sn;
        if (sr != 0.f || si != 0.f) {
            sn = 1.f / sqrtf(sr * sr + si * si);
        } else {
            const float2 sm = g_Smean[b];
            sn = 1.f / sqrtf(sm.x * sm.x + sm.y * sm.y);
        }
        const float dr = sp_re - sr, di = sp_im - si;
        const float r1r = (dr * dr - di * di) * bt0;  // complex (d)^2 * bt0
        const float r1i = (2.f * dr * di) * bt0;
        const float r2  = dr * dr * bt1;              // real part only
        a0 = (double)(sn * (r1r + r2));
        a1 = (double)(sn * r1i);

        const float vminv = (vm != 0.f) ? (1.f / vm) : (1.f / g_Vmmean[b]);
        const float vmag  = sqrtf(vr * vr + vi * vi);
        a2 = (double)(fabsf(vmag * (bt1 + bt2) - vm) * vminv);
        a3 = (double)(fabsf(vi * bt2) * vminv);

        const float2 l2 = *(const float2*)(labels + 2 * idx);
        const float e0 = vr - l2.x, e1 = vi - l2.y;
        a4 = (double)(e0 * e0) + (double)(e1 * e1);
    }

    for (int o = 16; o > 0; o >>= 1) {
        a0 += __shfl_down_sync(0xffffffffu, a0, o);
        a1 += __shfl_down_sync(0xffffffffu, a1, o);
        a2 += __shfl_down_sync(0xffffffffu, a2, o);
        a3 += __shfl_down_sync(0xffffffffu, a3, o);
        a4 += __shfl_down_sync(0xffffffffu, a4, o);
    }
    __shared__ double shd[5][NT / 32];
    if (lane == 0) {
        shd[0][wid] = a0; shd[1][wid] = a1; shd[2][wid] = a2;
        shd[3][wid] = a3; shd[4][wid] = a4;
    }
    __syncthreads();
    if (wid == 0) {
        a0 = (lane < NT / 32) ? shd[0][lane] : 0.0;
        a1 = (lane < NT / 32) ? shd[1][lane] : 0.0;
        a2 = (lane < NT / 32) ? shd[2][lane] : 0.0;
        a3 = (lane < NT / 32) ? shd[3][lane] : 0.0;
        a4 = (lane < NT / 32) ? shd[4][lane] : 0.0;
        for (int o = 4; o > 0; o >>= 1) {
            a0 += __shfl_down_sync(0xffffffffu, a0, o);
            a1 += __shfl_down_sync(0xffffffffu, a1, o);
            a2 += __shfl_down_sync(0xffffffffu, a2, o);
            a3 += __shfl_down_sync(0xffffffffu, a3, o);
            a4 += __shfl_down_sync(0xffffffffu, a4, o);
        }
        if (lane == 0) {                              // plain stores, no atomics
            g_part[blockIdx.x][0] = a0;
            g_part[blockIdx.x][1] = a1;
            g_part[blockIdx.x][2] = a2;
            g_part[blockIdx.x][3] = a3;
            g_part[blockIdx.x][4] = a4;
        }
    }

    // --- last-done block reduces partials and finalizes ---
    __shared__ int s_last;
    __syncthreads();
    if (tid == 0) {
        __threadfence();
        s_last = (atomicAdd(&g_done2, 1u) == gridDim.x - 1u);
    }
    __syncthreads();
    if (s_last) {
        __threadfence();
        double s0 = 0, s1 = 0, s2 = 0, s3 = 0, s4 = 0;
        for (int i = tid; i < (int)gridDim.x; i += NT) {
            s0 += g_part[i][0]; s1 += g_part[i][1]; s2 += g_part[i][2];
            s3 += g_part[i][3]; s4 += g_part[i][4];
        }
        for (int o = 16; o > 0; o >>= 1) {
            s0 += __shfl_down_sync(0xffffffffu, s0, o);
            s1 += __shfl_down_sync(0xffffffffu, s1, o);
            s2 += __shfl_down_sync(0xffffffffu, s2, o);
            s3 += __shfl_down_sync(0xffffffffu, s3, o);
            s4 += __shfl_down_sync(0xffffffffu, s4, o);
        }
        __shared__ double sh2[5][NT / 32];
        if (lane == 0) {
            sh2[0][wid] = s0; sh2[1][wid] = s1; sh2[2][wid] = s2;
            sh2[3][wid] = s3; sh2[4][wid] = s4;
        }
        __syncthreads();
        if (tid == 0) {
            s0 = s1 = s2 = s3 = s4 = 0.0;
            for (int w = 0; w < NT / 32; w++) {
                s0 += sh2[0][w]; s1 += sh2[1][w]; s2 += sh2[2][w];
                s3 += sh2[3][w]; s4 += sh2[4][w];
            }
            const double inv = 1.0 / (double)BN;
            const double d1r = s0 * inv;
            const double d1i = s1 * inv;
            const double d2  = s2 * inv;
            const double d3  = s3 * inv;
            const double mse = s4 / (double)(2 * BN);
            const double pr = d1r + d2 + d3;   // W1=W2=W3=1
            const double pi = d1i;
            const double lr = mse + 0.1 * pr;  // LMBDA = 0.1
            const double li = 0.1 * pi;
            if (out_size >= 10) {
                out[0] = (float)lr;  out[1] = (float)li;
                out[2] = (float)pr;  out[3] = (float)pi;
                out[4] = (float)d1r; out[5] = (float)d1i;
                out[6] = (float)d2;  out[7] = 0.f;
                out[8] = (float)d3;  out[9] = 0.f;
            } else {
                out[0] = (float)lr;
                if (out_size > 1) out[1] = (float)pr;
                if (out_size > 2) out[2] = (float)d1r;
                if (out_size > 3) out[3] = (float)d2;
                if (out_size > 4) out[4] = (float)d3;
            }
            g_done2 = 0u;
            g_epoch = g_epoch + 1ull;          // invalidate table entries (no wrap: 46 bits)
        }
    }
}

// ---------------------------------------------------------------------------
extern "C" void kernel_launch(void* const* d_in, const int* in_sizes, int n_in,
                              void* d_out, int out_size)
{
    const float* x       = (const float*)d_in[0];
    const float* ea      = (const float*)d_in[1];
    const int*   ei      = (const int*)  d_in[2];
    const float* outputs = (const float*)d_in[3];
    const float* labels  = (const float*)d_in[4];

    const int BN = in_sizes[3] / 2;        // B * N_BUSES
    const int B  = BN / N_BUSES;
    const int BE = in_sizes[2] / 2;        // B * E
    const int E  = BE / B;

    const int nbEdge = (BE + NT - 1) / NT;
    const int nbBus  = (BN + NT - 1) / NT;

    k1_build<<<nbEdge, NT>>>(x, ea, ei, outputs, B, BE, E);
    k3_terms<<<nbBus,  NT>>>(x, outputs, labels, (float*)d_out, out_size, BN);
}